// round 15
// baseline (speedup 1.0000x reference)
#include <cuda_runtime.h>
#include <cuda_bf16.h>
#include <cuda_fp16.h>
#include <cstdint>

// Problem constants (fixed by the dataset)
#define NNODES 50000
#define NEDGES 800000
#define FIN    512
#define HDIM   128
#define CDIM   64

#define SCAN_BLK 256
#define NB_SCAN  ((NNODES + SCAN_BLK - 1) / SCAN_BLK)   // 196

// ---------------------------------------------------------------------------
// Device scratch (no allocation allowed anywhere)
// ---------------------------------------------------------------------------
__device__ __half g_h1h [(size_t)NNODES * HDIM];  // x@W1 (pre-bias), fp16
__device__ float g_agg1[(size_t)NNODES * HDIM];   // layer-1 aggregation (fp32)
__device__ float g_h2  [(size_t)NNODES * CDIM];   // act(agg1)@W2 (fp32)
__device__ int   g_deg   [NNODES];
__device__ int   g_offs  [NNODES];
__device__ int   g_cursor[NNODES];
__device__ int   g_bsum  [NB_SCAN];
__device__ int2  g_bin   [NEDGES];
__device__ __nv_bfloat16 g_w1t_hi[HDIM * FIN];    // W1^T split-hi  [n=128][k=512]
__device__ __nv_bfloat16 g_w1t_lo[HDIM * FIN];    // W1^T split-lo
__device__ __nv_bfloat16 g_w2t_hi[CDIM * HDIM];   // W2^T split-hi  [n=64][k=128]
__device__ __nv_bfloat16 g_w2t_lo[CDIM * HDIM];   // W2^T split-lo

typedef struct __align__(8) { __half2 a, b; } half4_t;

// ---------------------------------------------------------------------------
// HMMA helpers (legacy warp-level tensor core path; sm_80+ baseline PTX)
// ---------------------------------------------------------------------------
__device__ __forceinline__ uint32_t smem_u32(const void* p) {
    uint32_t a;
    asm("{ .reg .u64 t; cvta.to.shared.u64 t, %1; cvt.u32.u64 %0, t; }" : "=r"(a) : "l"(p));
    return a;
}
__device__ __forceinline__ void ldsm_x4(uint32_t* r, uint32_t addr) {
    asm volatile("ldmatrix.sync.aligned.m8n8.x4.shared.b16 {%0,%1,%2,%3}, [%4];"
                 : "=r"(r[0]), "=r"(r[1]), "=r"(r[2]), "=r"(r[3]) : "r"(addr));
}
__device__ __forceinline__ void mma_bf16(float* c, const uint32_t* a, const uint32_t* b) {
    asm volatile(
        "mma.sync.aligned.m16n8k16.row.col.f32.bf16.bf16.f32 "
        "{%0,%1,%2,%3}, {%4,%5,%6,%7}, {%8,%9}, {%0,%1,%2,%3};"
        : "+f"(c[0]), "+f"(c[1]), "+f"(c[2]), "+f"(c[3])
        : "r"(a[0]), "r"(a[1]), "r"(a[2]), "r"(a[3]), "r"(b[0]), "r"(b[1]));
}
#define CP_ASYNC16(dst, src) \
    asm volatile("cp.async.cg.shared.global [%0], [%1], 16;" :: "r"(dst), "l"(src))
#define CP_COMMIT()  asm volatile("cp.async.commit_group;" ::: "memory")
#define CP_WAIT0()   asm volatile("cp.async.wait_group 0;" ::: "memory")

// fp32 -> (hi, lo) bf16 split; returns packed hi word, writes packed lo word.
__device__ __forceinline__ uint32_t split_pair(float a, float b, uint32_t& low) {
    __nv_bfloat16 ha = __float2bfloat16(a), hb = __float2bfloat16(b);
    __nv_bfloat16 la = __float2bfloat16(a - __bfloat162float(ha));
    __nv_bfloat16 lb = __float2bfloat16(b - __bfloat162float(hb));
    low = (uint32_t)__bfloat16_as_ushort(la) | ((uint32_t)__bfloat16_as_ushort(lb) << 16);
    return (uint32_t)__bfloat16_as_ushort(ha) | ((uint32_t)__bfloat16_as_ushort(hb) << 16);
}

// ===========================================================================
// Weight prep: transpose + bf16 split
// ===========================================================================
__global__ __launch_bounds__(256)
void w1prep_kernel(const float* __restrict__ W1) {
    int i = blockIdx.x * blockDim.x + threadIdx.x;
    if (i >= HDIM * FIN) return;
    int n = i & (HDIM - 1), k = i >> 7;
    float v = W1[k * HDIM + n];
    __nv_bfloat16 h = __float2bfloat16(v);
    g_w1t_hi[n * FIN + k] = h;
    g_w1t_lo[n * FIN + k] = __float2bfloat16(v - __bfloat162float(h));
}

__global__ __launch_bounds__(256)
void w2prep_kernel(const float* __restrict__ W2) {
    int i = blockIdx.x * blockDim.x + threadIdx.x;
    if (i >= CDIM * HDIM) return;
    int n = i & (CDIM - 1), k = i >> 6;
    float v = W2[k * CDIM + n];
    __nv_bfloat16 h = __float2bfloat16(v);
    g_w2t_hi[n * HDIM + k] = h;
    g_w2t_lo[n * HDIM + k] = __float2bfloat16(v - __bfloat162float(h));
}

// ===========================================================================
// CSR build: zero -> histogram -> 3-phase scan -> bin   (forked stream)
// ===========================================================================
__global__ __launch_bounds__(256)
void zero_deg_kernel() {
    int i = blockIdx.x * blockDim.x + threadIdx.x;
    if (i < NNODES) g_deg[i] = 0;
}

__global__ __launch_bounds__(256)
void hist_kernel(const int* __restrict__ dst) {
    int e = blockIdx.x * blockDim.x + threadIdx.x;
    if (e < NEDGES) atomicAdd(&g_deg[dst[e]], 1);
}

__global__ __launch_bounds__(SCAN_BLK)
void scan1_kernel() {
    __shared__ int sh[SCAN_BLK];
    int i = blockIdx.x * SCAN_BLK + threadIdx.x;
    int v = (i < NNODES) ? g_deg[i] : 0;
    sh[threadIdx.x] = v;
    __syncthreads();
    #pragma unroll
    for (int s = SCAN_BLK / 2; s > 0; s >>= 1) {
        if (threadIdx.x < s) sh[threadIdx.x] += sh[threadIdx.x + s];
        __syncthreads();
    }
    if (threadIdx.x == 0) g_bsum[blockIdx.x] = sh[0];
}

__global__ __launch_bounds__(SCAN_BLK)
void scan2_kernel() {
    __shared__ int sh[SCAN_BLK];
    int tid = threadIdx.x;
    int v = (tid < NB_SCAN) ? g_bsum[tid] : 0;
    sh[tid] = v;
    __syncthreads();
    #pragma unroll
    for (int s = 1; s < SCAN_BLK; s <<= 1) {
        int add = (tid >= s) ? sh[tid - s] : 0;
        __syncthreads();
        sh[tid] += add;
        __syncthreads();
    }
    if (tid < NB_SCAN) g_bsum[tid] = sh[tid] - v;
}

__global__ __launch_bounds__(SCAN_BLK)
void scan3_kernel() {
    __shared__ int sh[SCAN_BLK];
    int i = blockIdx.x * SCAN_BLK + threadIdx.x;
    int v = (i < NNODES) ? g_deg[i] : 0;
    sh[threadIdx.x] = v;
    __syncthreads();
    #pragma unroll
    for (int s = 1; s < SCAN_BLK; s <<= 1) {
        int add = (threadIdx.x >= s) ? sh[threadIdx.x - s] : 0;
        __syncthreads();
        sh[threadIdx.x] += add;
        __syncthreads();
    }
    if (i < NNODES) {
        int excl = sh[threadIdx.x] - v + g_bsum[blockIdx.x];
        g_offs[i]   = excl;
        g_cursor[i] = excl;
    }
}

__global__ __launch_bounds__(256)
void bin_kernel(const int* __restrict__ src, const int* __restrict__ dst,
                const float* __restrict__ ew) {
    int e = blockIdx.x * blockDim.x + threadIdx.x;
    if (e >= NEDGES) return;
    int d   = dst[e];
    int pos = atomicAdd(&g_cursor[d], 1);
    g_bin[pos] = make_int2(src[e], __float_as_int(ew[e]));
}

// ===========================================================================
// GEMM1 via legacy HMMA, 3-split emu: h1 = x @ W1  -> fp16 output
// CTA: 64(M) x 128(N); 8 warps 2x4; warp tile 32x32; BK=32 double-buffered.
// ===========================================================================
#define G1_BM    64
#define G1_BK    32
#define G1_LDB   40
#define G1_APL   (G1_BM * G1_LDB * 2)      // 5120 B per A plane
#define G1_BPL   (HDIM * G1_LDB * 2)       // 10240 B per B plane
#define G1_STG   (2 * G1_APL + 2 * G1_BPL) // 30720 B per stage
#define G1_SMEM  (2 * G1_STG)              // 61440 B
#define G1_NCH   (FIN / G1_BK)             // 16

#define OFF_AH 0
#define OFF_AL G1_APL
#define OFF_BH (2 * G1_APL)
#define OFF_BL (2 * G1_APL + G1_BPL)

__global__ __launch_bounds__(256)
void gemm1_hmma_kernel(const float* __restrict__ A, int M) {
    extern __shared__ char smem[];
    const uint32_t sb = smem_u32(smem);
    const int tid  = threadIdx.x;
    const int wid  = tid >> 5;
    const int lane = tid & 31;
    const int wm   = wid >> 2;
    const int wn   = wid & 3;
    const int m0   = blockIdx.x * G1_BM;

    const __nv_bfloat16* __restrict__ bhp = g_w1t_hi;
    const __nv_bfloat16* __restrict__ blp = g_w1t_lo;

    float acc[2][4][4];
    #pragma unroll
    for (int i = 0; i < 2; i++)
        #pragma unroll
        for (int j = 0; j < 4; j++)
            #pragma unroll
            for (int q = 0; q < 4; q++) acc[i][j][q] = 0.f;

    auto ldgA = [&](int k0, float4* ar) {
        #pragma unroll
        for (int p = 0; p < 2; p++) {
            int idx = tid + p * 256;
            int r   = idx >> 3;
            int c4  = idx & 7;
            float4 v = make_float4(0.f, 0.f, 0.f, 0.f);
            if (m0 + r < M) v = *(const float4*)&A[(size_t)(m0 + r) * FIN + k0 + c4 * 4];
            ar[p] = v;
        }
    };
    auto stsA = [&](uint32_t stg, const float4* ar) {
        #pragma unroll
        for (int p = 0; p < 2; p++) {
            int idx = tid + p * 256;
            int r   = idx >> 3;
            int c4  = idx & 7;
            uint32_t lo0, lo1;
            uint32_t hi0 = split_pair(ar[p].x, ar[p].y, lo0);
            uint32_t hi1 = split_pair(ar[p].z, ar[p].w, lo1);
            uint32_t off = (uint32_t)(r * (G1_LDB * 2) + c4 * 8);
            *(uint2*)(smem + (stg - sb) + OFF_AH + off) = make_uint2(hi0, hi1);
            *(uint2*)(smem + (stg - sb) + OFF_AL + off) = make_uint2(lo0, lo1);
        }
    };
    auto cpB = [&](int k0, uint32_t stg) {
        #pragma unroll
        for (int p = 0; p < 4; p++) {
            int idx = tid + p * 256;
            int pl  = idx >> 9;
            int r   = (idx & 511) >> 2;
            int sg  = idx & 3;
            const __nv_bfloat16* src =
                (pl ? blp : bhp) + (size_t)r * FIN + k0 + sg * 8;
            uint32_t dst = stg + (pl ? OFF_BL : OFF_BH)
                         + (uint32_t)(r * (G1_LDB * 2) + sg * 16);
            CP_ASYNC16(dst, src);
        }
        CP_COMMIT();
    };

    float4 ar[2];
    ldgA(0, ar);
    cpB(0, sb);
    stsA(sb, ar);
    CP_WAIT0();
    __syncthreads();

    const int arow  = (lane & 15);
    const int acol8 = (lane >> 4) * 8;
    const int bg    = lane >> 3;
    const int brow  = ((bg >> 1) * 8) + (lane & 7);
    const int bcol8 = (bg & 1) * 8;

    for (int c = 0; c < G1_NCH; c++) {
        const uint32_t cur = sb + (uint32_t)((c & 1) * G1_STG);
        const uint32_t nxt = sb + (uint32_t)(((c + 1) & 1) * G1_STG);

        if (c + 1 < G1_NCH) {
            ldgA((c + 1) * G1_BK, ar);
            cpB((c + 1) * G1_BK, nxt);
        }

        #pragma unroll
        for (int kk = 0; kk < G1_BK; kk += 16) {
            uint32_t afh[2][4], afl[2][4];
            #pragma unroll
            for (int am = 0; am < 2; am++) {
                uint32_t aoff = (uint32_t)((wm * 32 + am * 16 + arow) * (G1_LDB * 2)
                                           + (kk + acol8) * 2);
                ldsm_x4(afh[am], cur + OFF_AH + aoff);
                ldsm_x4(afl[am], cur + OFF_AL + aoff);
            }
            #pragma unroll
            for (int bp = 0; bp < 2; bp++) {
                uint32_t boff = (uint32_t)((wn * 32 + bp * 16 + brow) * (G1_LDB * 2)
                                           + (kk + bcol8) * 2);
                uint32_t bfh[4], bfl[4];
                ldsm_x4(bfh, cur + OFF_BH + boff);
                ldsm_x4(bfl, cur + OFF_BL + boff);
                #pragma unroll
                for (int am = 0; am < 2; am++) {
                    #pragma unroll
                    for (int j = 0; j < 2; j++) {
                        float* cc = acc[am][bp * 2 + j];
                        mma_bf16(cc, afh[am], bfh + 2 * j);
                        mma_bf16(cc, afh[am], bfl + 2 * j);
                        mma_bf16(cc, afl[am], bfh + 2 * j);
                    }
                }
            }
        }

        if (c + 1 < G1_NCH) {
            stsA(nxt, ar);
            CP_WAIT0();
        }
        __syncthreads();
    }

    // epilogue: fp16 stores (half2 per fragment pair)
    const int erow = lane >> 2;
    const int ecol = (lane & 3) * 2;
    #pragma unroll
    for (int am = 0; am < 2; am++) {
        int r0 = m0 + wm * 32 + am * 16 + erow;
        #pragma unroll
        for (int an = 0; an < 4; an++) {
            int colb = wn * 32 + an * 8 + ecol;
            if (r0 < M)
                *(__half2*)&g_h1h[(size_t)r0 * HDIM + colb] =
                    __floats2half2_rn(acc[am][an][0], acc[am][an][1]);
            if (r0 + 8 < M)
                *(__half2*)&g_h1h[(size_t)(r0 + 8) * HDIM + colb] =
                    __floats2half2_rn(acc[am][an][2], acc[am][an][3]);
        }
    }
}

// ===========================================================================
// CSR aggregation, layer 1: fp16 gathers, fp32 accumulate, unroll-4
// ===========================================================================
__device__ __forceinline__ void acc_h4(float4& a, float w, half4_t v) {
    float2 f0 = __half22float2(v.a);
    float2 f1 = __half22float2(v.b);
    a.x = fmaf(w, f0.x, a.x); a.y = fmaf(w, f0.y, a.y);
    a.z = fmaf(w, f1.x, a.z); a.w = fmaf(w, f1.y, a.w);
}

__global__ __launch_bounds__(256)
void agg1_csr_kernel() {
    int warp = (blockIdx.x * blockDim.x + threadIdx.x) >> 5;
    int lane = threadIdx.x & 31;
    if (warp >= NNODES) return;
    int e  = g_offs[warp];
    int end = e + g_deg[warp];

    float4 a0 = make_float4(0.f, 0.f, 0.f, 0.f);
    float4 a1 = make_float4(0.f, 0.f, 0.f, 0.f);
    float4 a2 = make_float4(0.f, 0.f, 0.f, 0.f);
    float4 a3 = make_float4(0.f, 0.f, 0.f, 0.f);
    const __half* __restrict__ h = g_h1h;

    for (; e + 3 < end; e += 4) {
        int2 p0 = g_bin[e],     p1 = g_bin[e + 1];
        int2 p2 = g_bin[e + 2], p3 = g_bin[e + 3];
        half4_t v0 = *(const half4_t*)&h[(size_t)p0.x * HDIM + lane * 4];
        half4_t v1 = *(const half4_t*)&h[(size_t)p1.x * HDIM + lane * 4];
        half4_t v2 = *(const half4_t*)&h[(size_t)p2.x * HDIM + lane * 4];
        half4_t v3 = *(const half4_t*)&h[(size_t)p3.x * HDIM + lane * 4];
        acc_h4(a0, __int_as_float(p0.y), v0);
        acc_h4(a1, __int_as_float(p1.y), v1);
        acc_h4(a2, __int_as_float(p2.y), v2);
        acc_h4(a3, __int_as_float(p3.y), v3);
    }
    for (; e < end; e++) {
        int2 p0 = g_bin[e];
        half4_t v0 = *(const half4_t*)&h[(size_t)p0.x * HDIM + lane * 4];
        acc_h4(a0, __int_as_float(p0.y), v0);
    }
    a0.x += a1.x + a2.x + a3.x;
    a0.y += a1.y + a2.y + a3.y;
    a0.z += a1.z + a2.z + a3.z;
    a0.w += a1.w + a2.w + a3.w;
    *(float4*)&g_agg1[(size_t)warp * HDIM + lane * 4] = a0;
}

// ===========================================================================
// GEMM2 via legacy HMMA, 3-split emu, activation fused into the A loader:
//   h2 = act(agg1) @ W2 ; act(v) = relu(v + b1) * (mask >= 0.5 ? 2 : 0)
// CTA: 128(M) x 64(N); 8 warps 4x2; warp tile 32x32; BK=32 double-buffered.
// ===========================================================================
#define G2_BM    128
#define G2_BK    32
#define G2_APL   (G2_BM * G1_LDB * 2)      // 10240 B per A plane
#define G2_BPL   (CDIM * G1_LDB * 2)       // 5120 B per B plane
#define G2_STG   (2 * G2_APL + 2 * G2_BPL) // 30720 B per stage
#define G2_SMEM  (2 * G2_STG)              // 61440 B
#define G2_NCH   (HDIM / G2_BK)            // 4

#define OFF2_AH 0
#define OFF2_AL G2_APL
#define OFF2_BH (2 * G2_APL)
#define OFF2_BL (2 * G2_APL + G2_BPL)

__global__ __launch_bounds__(256)
void gemm2_hmma_kernel(const float* __restrict__ b1, const float* __restrict__ mask,
                       int M) {
    extern __shared__ char smem[];
    const uint32_t sb = smem_u32(smem);
    const int tid  = threadIdx.x;
    const int wid  = tid >> 5;
    const int lane = tid & 31;
    const int wm   = wid >> 1;
    const int wn   = wid & 1;
    const int m0   = blockIdx.x * G2_BM;

    const __nv_bfloat16* __restrict__ bhp = g_w2t_hi;
    const __nv_bfloat16* __restrict__ blp = g_w2t_lo;

    float acc[2][4][4];
    #pragma unroll
    for (int i = 0; i < 2; i++)
        #pragma unroll
        for (int j = 0; j < 4; j++)
            #pragma unroll
            for (int q = 0; q < 4; q++) acc[i][j][q] = 0.f;

    auto ldgA = [&](int k0, float4* ar) {
        #pragma unroll
        for (int p = 0; p < 4; p++) {
            int idx = tid + p * 256;
            int r   = idx >> 3;
            int c4  = idx & 7;
            float4 v = make_float4(0.f, 0.f, 0.f, 0.f);
            if (m0 + r < M) {
                size_t base = (size_t)(m0 + r) * HDIM + k0 + c4 * 4;
                v          = *(const float4*)&g_agg1[base];
                float4 mk  = *(const float4*)&mask[base];
                float4 bb  = *(const float4*)&b1[k0 + c4 * 4];
                v.x = fmaxf(v.x + bb.x, 0.f) * (mk.x >= 0.5f ? 2.f : 0.f);
                v.y = fmaxf(v.y + bb.y, 0.f) * (mk.y >= 0.5f ? 2.f : 0.f);
                v.z = fmaxf(v.z + bb.z, 0.f) * (mk.z >= 0.5f ? 2.f : 0.f);
                v.w = fmaxf(v.w + bb.w, 0.f) * (mk.w >= 0.5f ? 2.f : 0.f);
            }
            ar[p] = v;
        }
    };
    auto stsA = [&](uint32_t stg, const float4* ar) {
        #pragma unroll
        for (int p = 0; p < 4; p++) {
            int idx = tid + p * 256;
            int r   = idx >> 3;
            int c4  = idx & 7;
            uint32_t lo0, lo1;
            uint32_t hi0 = split_pair(ar[p].x, ar[p].y, lo0);
            uint32_t hi1 = split_pair(ar[p].z, ar[p].w, lo1);
            uint32_t off = (uint32_t)(r * (G1_LDB * 2) + c4 * 8);
            *(uint2*)(smem + (stg - sb) + OFF2_AH + off) = make_uint2(hi0, hi1);
            *(uint2*)(smem + (stg - sb) + OFF2_AL + off) = make_uint2(lo0, lo1);
        }
    };
    auto cpB = [&](int k0, uint32_t stg) {
        #pragma unroll
        for (int p = 0; p < 2; p++) {
            int idx = tid + p * 256;
            int pl  = idx >> 8;
            int r   = (idx & 255) >> 2;
            int sg  = idx & 3;
            const __nv_bfloat16* src =
                (pl ? blp : bhp) + (size_t)r * HDIM + k0 + sg * 8;
            uint32_t dst = stg + (pl ? OFF2_BL : OFF2_BH)
                         + (uint32_t)(r * (G1_LDB * 2) + sg * 16);
            CP_ASYNC16(dst, src);
        }
        CP_COMMIT();
    };

    float4 ar[4];
    ldgA(0, ar);
    cpB(0, sb);
    stsA(sb, ar);
    CP_WAIT0();
    __syncthreads();

    const int arow  = (lane & 15);
    const int acol8 = (lane >> 4) * 8;
    const int bg    = lane >> 3;
    const int brow  = ((bg >> 1) * 8) + (lane & 7);
    const int bcol8 = (bg & 1) * 8;

    for (int c = 0; c < G2_NCH; c++) {
        const uint32_t cur = sb + (uint32_t)((c & 1) * G2_STG);
        const uint32_t nxt = sb + (uint32_t)(((c + 1) & 1) * G2_STG);

        if (c + 1 < G2_NCH) {
            ldgA((c + 1) * G2_BK, ar);
            cpB((c + 1) * G2_BK, nxt);
        }

        #pragma unroll
        for (int kk = 0; kk < G2_BK; kk += 16) {
            uint32_t afh[2][4], afl[2][4];
            #pragma unroll
            for (int am = 0; am < 2; am++) {
                uint32_t aoff = (uint32_t)((wm * 32 + am * 16 + arow) * (G1_LDB * 2)
                                           + (kk + acol8) * 2);
                ldsm_x4(afh[am], cur + OFF2_AH + aoff);
                ldsm_x4(afl[am], cur + OFF2_AL + aoff);
            }
            #pragma unroll
            for (int bp = 0; bp < 2; bp++) {
                uint32_t boff = (uint32_t)((wn * 32 + bp * 16 + brow) * (G1_LDB * 2)
                                           + (kk + bcol8) * 2);
                uint32_t bfh[4], bfl[4];
                ldsm_x4(bfh, cur + OFF2_BH + boff);
                ldsm_x4(bfl, cur + OFF2_BL + boff);
                #pragma unroll
                for (int am = 0; am < 2; am++) {
                    #pragma unroll
                    for (int j = 0; j < 2; j++) {
                        float* cc = acc[am][bp * 2 + j];
                        mma_bf16(cc, afh[am], bfh + 2 * j);
                        mma_bf16(cc, afh[am], bfl + 2 * j);
                        mma_bf16(cc, afl[am], bfh + 2 * j);
                    }
                }
            }
        }

        if (c + 1 < G2_NCH) {
            stsA(nxt, ar);
            CP_WAIT0();
        }
        __syncthreads();
    }

    const int erow = lane >> 2;
    const int ecol = (lane & 3) * 2;
    #pragma unroll
    for (int am = 0; am < 2; am++) {
        int r0 = m0 + wm * 32 + am * 16 + erow;
        #pragma unroll
        for (int an = 0; an < 4; an++) {
            int colb = wn * 32 + an * 8 + ecol;
            if (r0 < M)
                *(float2*)&g_h2[(size_t)r0 * CDIM + colb] =
                    make_float2(acc[am][an][0], acc[am][an][1]);
            if (r0 + 8 < M)
                *(float2*)&g_h2[(size_t)(r0 + 8) * CDIM + colb] =
                    make_float2(acc[am][an][2], acc[am][an][3]);
        }
    }
}

// ===========================================================================
// CSR aggregation, layer 2, fused bias + log-softmax, unroll-4 (fp32 h2)
// ===========================================================================
__global__ __launch_bounds__(256)
void agg2_softmax_kernel(const float* __restrict__ b2, float* __restrict__ out) {
    int warp = (blockIdx.x * blockDim.x + threadIdx.x) >> 5;
    int lane = threadIdx.x & 31;
    if (warp >= NNODES) return;
    int e  = g_offs[warp];
    int end = e + g_deg[warp];

    float2 a0 = make_float2(0.f, 0.f), a1 = make_float2(0.f, 0.f);
    float2 a2 = make_float2(0.f, 0.f), a3 = make_float2(0.f, 0.f);
    const float* __restrict__ h = g_h2;

    for (; e + 3 < end; e += 4) {
        int2 p0 = g_bin[e],     p1 = g_bin[e + 1];
        int2 p2 = g_bin[e + 2], p3 = g_bin[e + 3];
        float w0 = __int_as_float(p0.y), w1 = __int_as_float(p1.y);
        float w2 = __int_as_float(p2.y), w3 = __int_as_float(p3.y);
        float2 v0 = *(const float2*)&h[(size_t)p0.x * CDIM + lane * 2];
        float2 v1 = *(const float2*)&h[(size_t)p1.x * CDIM + lane * 2];
        float2 v2 = *(const float2*)&h[(size_t)p2.x * CDIM + lane * 2];
        float2 v3 = *(const float2*)&h[(size_t)p3.x * CDIM + lane * 2];
        a0.x = fmaf(w0, v0.x, a0.x); a0.y = fmaf(w0, v0.y, a0.y);
        a1.x = fmaf(w1, v1.x, a1.x); a1.y = fmaf(w1, v1.y, a1.y);
        a2.x = fmaf(w2, v2.x, a2.x); a2.y = fmaf(w2, v2.y, a2.y);
        a3.x = fmaf(w3, v3.x, a3.x); a3.y = fmaf(w3, v3.y, a3.y);
    }
    for (; e < end; e++) {
        int2 p0 = g_bin[e];
        float w0 = __int_as_float(p0.y);
        float2 v0 = *(const float2*)&h[(size_t)p0.x * CDIM + lane * 2];
        a0.x = fmaf(w0, v0.x, a0.x); a0.y = fmaf(w0, v0.y, a0.y);
    }
    float2 bb = *(const float2*)&b2[lane * 2];
    float vx = a0.x + a1.x + a2.x + a3.x + bb.x;
    float vy = a0.y + a1.y + a2.y + a3.y + bb.y;

    float m = fmaxf(vx, vy);
    #pragma unroll
    for (int o = 16; o > 0; o >>= 1) m = fmaxf(m, __shfl_xor_sync(0xFFFFFFFFu, m, o));
    float s = expf(vx - m) + expf(vy - m);
    #pragma unroll
    for (int o = 16; o > 0; o >>= 1) s += __shfl_xor_sync(0xFFFFFFFFu, s, o);
    float lse = m + logf(s);
    *(float2*)&out[(size_t)warp * CDIM + lane * 2] = make_float2(vx - lse, vy - lse);
}

// ===========================================================================
// Launch — CSR build + w2prep forked onto a second stream, under GEMM1.
// ===========================================================================
extern "C" void kernel_launch(void* const* d_in, const int* in_sizes, int n_in,
                              void* d_out, int out_size) {
    const float* x    = (const float*)d_in[0];   // [N, 512]
    const float* ew   = (const float*)d_in[1];   // [E]
    const float* W1   = (const float*)d_in[2];   // [512, 128]
    const float* b1   = (const float*)d_in[3];   // [128]
    const float* W2   = (const float*)d_in[4];   // [128, 64]
    const float* b2   = (const float*)d_in[5];   // [64]
    const float* mask = (const float*)d_in[6];   // [N, 128]
    const int*   ei   = (const int*)d_in[7];     // [2, E]
    float* out = (float*)d_out;

    const int N = NNODES, E = NEDGES;
    const int* src = ei;
    const int* dst = ei + E;

    static cudaStream_t s2 = nullptr;
    static cudaEvent_t  evFork = nullptr, evJoin = nullptr;
    if (!s2) {
        cudaStreamCreateWithFlags(&s2, cudaStreamNonBlocking);
        cudaEventCreateWithFlags(&evFork, cudaEventDisableTiming);
        cudaEventCreateWithFlags(&evJoin, cudaEventDisableTiming);
        cudaFuncSetAttribute(gemm1_hmma_kernel,
                             cudaFuncAttributeMaxDynamicSharedMemorySize, G1_SMEM);
        cudaFuncSetAttribute(gemm2_hmma_kernel,
                             cudaFuncAttributeMaxDynamicSharedMemorySize, G2_SMEM);
    }

    // --- fork: CSR build + W2 prep on s2 (all hidden under gemm1) ---
    cudaEventRecord(evFork, 0);
    cudaStreamWaitEvent(s2, evFork, 0);

    w2prep_kernel<<<(CDIM * HDIM + 255) / 256, 256, 0, s2>>>(W2);
    zero_deg_kernel<<<(N + 255) / 256, 256, 0, s2>>>();
    hist_kernel<<<(E + 255) / 256, 256, 0, s2>>>(dst);
    scan1_kernel<<<NB_SCAN, SCAN_BLK, 0, s2>>>();
    scan2_kernel<<<1, SCAN_BLK, 0, s2>>>();
    scan3_kernel<<<NB_SCAN, SCAN_BLK, 0, s2>>>();
    bin_kernel<<<(E + 255) / 256, 256, 0, s2>>>(src, dst, ew);
    cudaEventRecord(evJoin, s2);

    // --- main stream: W1 split prep, then HMMA GEMM1 ---
    w1prep_kernel<<<(HDIM * FIN + 255) / 256, 256>>>(W1);
    gemm1_hmma_kernel<<<(N + G1_BM - 1) / G1_BM, 256, G1_SMEM>>>(x, N);

    // --- join: aggregation needs both h1 and the CSR bins ---
    cudaStreamWaitEvent(0, evJoin, 0);
    agg1_csr_kernel<<<(N * 32 + 255) / 256, 256>>>();

    // --- layer 2 (HMMA, activation fused in loader) ---
    gemm2_hmma_kernel<<<(N + G2_BM - 1) / G2_BM, 256, G2_SMEM>>>(b1, mask, N);
    agg2_softmax_kernel<<<(N * 32 + 255) / 256, 256>>>(b2, out);
}

// round 16
// speedup vs baseline: 1.1872x; 1.1872x over previous
#include <cuda_runtime.h>
#include <cuda_bf16.h>
#include <cuda_fp16.h>
#include <cstdint>

// Problem constants (fixed by the dataset)
#define NNODES 50000
#define NEDGES 800000
#define FIN    512
#define HDIM   128
#define CDIM   64

#define SCAN_BLK 256
#define NB_SCAN  ((NNODES + SCAN_BLK - 1) / SCAN_BLK)   // 196

// ---------------------------------------------------------------------------
// Device scratch (no allocation allowed anywhere)
// ---------------------------------------------------------------------------
__device__ __half g_h1h [(size_t)NNODES * HDIM];  // x@W1 (pre-bias), fp16
__device__ float g_agg1[(size_t)NNODES * HDIM];   // layer-1 aggregation (fp32)
__device__ float g_h2  [(size_t)NNODES * CDIM];   // act(agg1)@W2 (fp32)
__device__ int   g_deg   [NNODES];
__device__ int   g_offs  [NNODES];
__device__ int   g_cursor[NNODES];
__device__ int   g_bsum  [NB_SCAN];
__device__ int2  g_bin   [NEDGES];
__device__ __half        g_w1t_h [HDIM * FIN];    // W1^T fp16 (single plane)
__device__ __nv_bfloat16 g_w2t_hi[CDIM * HDIM];   // W2^T split-hi  [n=64][k=128]
__device__ __nv_bfloat16 g_w2t_lo[CDIM * HDIM];   // W2^T split-lo

typedef struct __align__(8) { __half2 a, b; } half4_t;

// ---------------------------------------------------------------------------
// HMMA helpers (legacy warp-level tensor core path; sm_80+ baseline PTX)
// ---------------------------------------------------------------------------
__device__ __forceinline__ uint32_t smem_u32(const void* p) {
    uint32_t a;
    asm("{ .reg .u64 t; cvta.to.shared.u64 t, %1; cvt.u32.u64 %0, t; }" : "=r"(a) : "l"(p));
    return a;
}
__device__ __forceinline__ void ldsm_x4(uint32_t* r, uint32_t addr) {
    asm volatile("ldmatrix.sync.aligned.m8n8.x4.shared.b16 {%0,%1,%2,%3}, [%4];"
                 : "=r"(r[0]), "=r"(r[1]), "=r"(r[2]), "=r"(r[3]) : "r"(addr));
}
__device__ __forceinline__ void mma_bf16(float* c, const uint32_t* a, const uint32_t* b) {
    asm volatile(
        "mma.sync.aligned.m16n8k16.row.col.f32.bf16.bf16.f32 "
        "{%0,%1,%2,%3}, {%4,%5,%6,%7}, {%8,%9}, {%0,%1,%2,%3};"
        : "+f"(c[0]), "+f"(c[1]), "+f"(c[2]), "+f"(c[3])
        : "r"(a[0]), "r"(a[1]), "r"(a[2]), "r"(a[3]), "r"(b[0]), "r"(b[1]));
}
__device__ __forceinline__ void mma_fp16(float* c, const uint32_t* a, const uint32_t* b) {
    asm volatile(
        "mma.sync.aligned.m16n8k16.row.col.f32.f16.f16.f32 "
        "{%0,%1,%2,%3}, {%4,%5,%6,%7}, {%8,%9}, {%0,%1,%2,%3};"
        : "+f"(c[0]), "+f"(c[1]), "+f"(c[2]), "+f"(c[3])
        : "r"(a[0]), "r"(a[1]), "r"(a[2]), "r"(a[3]), "r"(b[0]), "r"(b[1]));
}
#define CP_ASYNC16(dst, src) \
    asm volatile("cp.async.cg.shared.global [%0], [%1], 16;" :: "r"(dst), "l"(src))
#define CP_COMMIT()  asm volatile("cp.async.commit_group;" ::: "memory")
#define CP_WAIT0()   asm volatile("cp.async.wait_group 0;" ::: "memory")

// fp32 -> (hi, lo) bf16 split; returns packed hi word, writes packed lo word.
__device__ __forceinline__ uint32_t split_pair(float a, float b, uint32_t& low) {
    __nv_bfloat16 ha = __float2bfloat16(a), hb = __float2bfloat16(b);
    __nv_bfloat16 la = __float2bfloat16(a - __bfloat162float(ha));
    __nv_bfloat16 lb = __float2bfloat16(b - __bfloat162float(hb));
    low = (uint32_t)__bfloat16_as_ushort(la) | ((uint32_t)__bfloat16_as_ushort(lb) << 16);
    return (uint32_t)__bfloat16_as_ushort(ha) | ((uint32_t)__bfloat16_as_ushort(hb) << 16);
}

// ===========================================================================
// Weight prep
// ===========================================================================
__global__ __launch_bounds__(256)
void w1prep_kernel(const float* __restrict__ W1) {   // fp16 single plane
    int i = blockIdx.x * blockDim.x + threadIdx.x;
    if (i >= HDIM * FIN) return;
    int n = i & (HDIM - 1), k = i >> 7;
    g_w1t_h[n * FIN + k] = __float2half_rn(W1[k * HDIM + n]);
}

__global__ __launch_bounds__(256)
void w2prep_kernel(const float* __restrict__ W2) {   // bf16 split planes
    int i = blockIdx.x * blockDim.x + threadIdx.x;
    if (i >= CDIM * HDIM) return;
    int n = i & (CDIM - 1), k = i >> 6;
    float v = W2[k * CDIM + n];
    __nv_bfloat16 h = __float2bfloat16(v);
    g_w2t_hi[n * HDIM + k] = h;
    g_w2t_lo[n * HDIM + k] = __float2bfloat16(v - __bfloat162float(h));
}

// ===========================================================================
// CSR build: zero -> histogram -> 3-phase scan -> bin   (forked stream)
// ===========================================================================
__global__ __launch_bounds__(256)
void zero_deg_kernel() {
    int i = blockIdx.x * blockDim.x + threadIdx.x;
    if (i < NNODES) g_deg[i] = 0;
}

__global__ __launch_bounds__(256)
void hist_kernel(const int* __restrict__ dst) {
    int e = blockIdx.x * blockDim.x + threadIdx.x;
    if (e < NEDGES) atomicAdd(&g_deg[dst[e]], 1);
}

__global__ __launch_bounds__(SCAN_BLK)
void scan1_kernel() {
    __shared__ int sh[SCAN_BLK];
    int i = blockIdx.x * SCAN_BLK + threadIdx.x;
    int v = (i < NNODES) ? g_deg[i] : 0;
    sh[threadIdx.x] = v;
    __syncthreads();
    #pragma unroll
    for (int s = SCAN_BLK / 2; s > 0; s >>= 1) {
        if (threadIdx.x < s) sh[threadIdx.x] += sh[threadIdx.x + s];
        __syncthreads();
    }
    if (threadIdx.x == 0) g_bsum[blockIdx.x] = sh[0];
}

__global__ __launch_bounds__(SCAN_BLK)
void scan2_kernel() {
    __shared__ int sh[SCAN_BLK];
    int tid = threadIdx.x;
    int v = (tid < NB_SCAN) ? g_bsum[tid] : 0;
    sh[tid] = v;
    __syncthreads();
    #pragma unroll
    for (int s = 1; s < SCAN_BLK; s <<= 1) {
        int add = (tid >= s) ? sh[tid - s] : 0;
        __syncthreads();
        sh[tid] += add;
        __syncthreads();
    }
    if (tid < NB_SCAN) g_bsum[tid] = sh[tid] - v;
}

__global__ __launch_bounds__(SCAN_BLK)
void scan3_kernel() {
    __shared__ int sh[SCAN_BLK];
    int i = blockIdx.x * SCAN_BLK + threadIdx.x;
    int v = (i < NNODES) ? g_deg[i] : 0;
    sh[threadIdx.x] = v;
    __syncthreads();
    #pragma unroll
    for (int s = 1; s < SCAN_BLK; s <<= 1) {
        int add = (threadIdx.x >= s) ? sh[threadIdx.x - s] : 0;
        __syncthreads();
        sh[threadIdx.x] += add;
        __syncthreads();
    }
    if (i < NNODES) {
        int excl = sh[threadIdx.x] - v + g_bsum[blockIdx.x];
        g_offs[i]   = excl;
        g_cursor[i] = excl;
    }
}

__global__ __launch_bounds__(256)
void bin_kernel(const int* __restrict__ src, const int* __restrict__ dst,
                const float* __restrict__ ew) {
    int e = blockIdx.x * blockDim.x + threadIdx.x;
    if (e >= NEDGES) return;
    int d   = dst[e];
    int pos = atomicAdd(&g_cursor[d], 1);
    g_bin[pos] = make_int2(src[e], __float_as_int(ew[e]));
}

// ===========================================================================
// GEMM1 via legacy HMMA, SINGLE fp16 MMA (no split): h1 = fp16(x) @ fp16(W1)
// Error: fp16 per-term ~6e-4, averaged down by K=512 + agg(16) + gemm2(128)
// reductions (calibrated by R15: fp16 h1 quantization -> 5.8e-5 final).
// CTA: 64(M) x 128(N); 8 warps 2x4; warp tile 32x32; BK=32 double-buffered.
// ===========================================================================
#define G1_BM    64
#define G1_BK    32
#define G1_LDB   40
#define G1_APL   (G1_BM * G1_LDB * 2)      // 5120 B  A plane (fp16)
#define G1_BPL   (HDIM * G1_LDB * 2)       // 10240 B B plane (fp16)
#define G1_STG   (G1_APL + G1_BPL)         // 15360 B per stage
#define G1_SMEM  (2 * G1_STG)              // 30720 B
#define G1_NCH   (FIN / G1_BK)             // 16

#define OFF_A 0
#define OFF_B G1_APL

__global__ __launch_bounds__(256)
void gemm1_hmma_kernel(const float* __restrict__ A, int M) {
    extern __shared__ char smem[];
    const uint32_t sb = smem_u32(smem);
    const int tid  = threadIdx.x;
    const int wid  = tid >> 5;
    const int lane = tid & 31;
    const int wm   = wid >> 2;
    const int wn   = wid & 3;
    const int m0   = blockIdx.x * G1_BM;

    const __half* __restrict__ bp = g_w1t_h;

    float acc[2][4][4];
    #pragma unroll
    for (int i = 0; i < 2; i++)
        #pragma unroll
        for (int j = 0; j < 4; j++)
            #pragma unroll
            for (int q = 0; q < 4; q++) acc[i][j][q] = 0.f;

    auto ldgA = [&](int k0, float4* ar) {
        #pragma unroll
        for (int p = 0; p < 2; p++) {
            int idx = tid + p * 256;
            int r   = idx >> 3;
            int c4  = idx & 7;
            float4 v = make_float4(0.f, 0.f, 0.f, 0.f);
            if (m0 + r < M) v = *(const float4*)&A[(size_t)(m0 + r) * FIN + k0 + c4 * 4];
            ar[p] = v;
        }
    };
    auto stsA = [&](uint32_t stg, const float4* ar) {
        #pragma unroll
        for (int p = 0; p < 2; p++) {
            int idx = tid + p * 256;
            int r   = idx >> 3;
            int c4  = idx & 7;
            __half2 h0 = __floats2half2_rn(ar[p].x, ar[p].y);
            __half2 h1 = __floats2half2_rn(ar[p].z, ar[p].w);
            uint32_t off = (uint32_t)(r * (G1_LDB * 2) + c4 * 8);
            *(__half2*)(smem + (stg - sb) + OFF_A + off)     = h0;
            *(__half2*)(smem + (stg - sb) + OFF_A + off + 4) = h1;
        }
    };
    auto cpB = [&](int k0, uint32_t stg) {
        // B tile: 128 n-rows x 32 k fp16 = 512 x 16B chunks
        #pragma unroll
        for (int p = 0; p < 2; p++) {
            int idx = tid + p * 256;
            int r   = idx >> 2;           // 0..127
            int sg  = idx & 3;
            const __half* src = bp + (size_t)r * FIN + k0 + sg * 8;
            uint32_t dst = stg + OFF_B + (uint32_t)(r * (G1_LDB * 2) + sg * 16);
            CP_ASYNC16(dst, src);
        }
        CP_COMMIT();
    };

    float4 ar[2];
    ldgA(0, ar);
    cpB(0, sb);
    stsA(sb, ar);
    CP_WAIT0();
    __syncthreads();

    const int arow  = (lane & 15);
    const int acol8 = (lane >> 4) * 8;
    const int bg    = lane >> 3;
    const int brow  = ((bg >> 1) * 8) + (lane & 7);
    const int bcol8 = (bg & 1) * 8;

    for (int c = 0; c < G1_NCH; c++) {
        const uint32_t cur = sb + (uint32_t)((c & 1) * G1_STG);
        const uint32_t nxt = sb + (uint32_t)(((c + 1) & 1) * G1_STG);

        if (c + 1 < G1_NCH) {
            ldgA((c + 1) * G1_BK, ar);
            cpB((c + 1) * G1_BK, nxt);
        }

        #pragma unroll
        for (int kk = 0; kk < G1_BK; kk += 16) {
            uint32_t af[2][4];
            #pragma unroll
            for (int am = 0; am < 2; am++) {
                uint32_t aoff = (uint32_t)((wm * 32 + am * 16 + arow) * (G1_LDB * 2)
                                           + (kk + acol8) * 2);
                ldsm_x4(af[am], cur + OFF_A + aoff);
            }
            #pragma unroll
            for (int bp2 = 0; bp2 < 2; bp2++) {
                uint32_t boff = (uint32_t)((wn * 32 + bp2 * 16 + brow) * (G1_LDB * 2)
                                           + (kk + bcol8) * 2);
                uint32_t bf[4];
                ldsm_x4(bf, cur + OFF_B + boff);
                #pragma unroll
                for (int am = 0; am < 2; am++) {
                    #pragma unroll
                    for (int j = 0; j < 2; j++)
                        mma_fp16(acc[am][bp2 * 2 + j], af[am], bf + 2 * j);
                }
            }
        }

        if (c + 1 < G1_NCH) {
            stsA(nxt, ar);
            CP_WAIT0();
        }
        __syncthreads();
    }

    // epilogue: fp16 stores (half2 per fragment pair)
    const int erow = lane >> 2;
    const int ecol = (lane & 3) * 2;
    #pragma unroll
    for (int am = 0; am < 2; am++) {
        int r0 = m0 + wm * 32 + am * 16 + erow;
        #pragma unroll
        for (int an = 0; an < 4; an++) {
            int colb = wn * 32 + an * 8 + ecol;
            if (r0 < M)
                *(__half2*)&g_h1h[(size_t)r0 * HDIM + colb] =
                    __floats2half2_rn(acc[am][an][0], acc[am][an][1]);
            if (r0 + 8 < M)
                *(__half2*)&g_h1h[(size_t)(r0 + 8) * HDIM + colb] =
                    __floats2half2_rn(acc[am][an][2], acc[am][an][3]);
        }
    }
}

// ===========================================================================
// CSR aggregation, layer 1: fp16 gathers, fp32 accumulate, unroll-4
// ===========================================================================
__device__ __forceinline__ void acc_h4(float4& a, float w, half4_t v) {
    float2 f0 = __half22float2(v.a);
    float2 f1 = __half22float2(v.b);
    a.x = fmaf(w, f0.x, a.x); a.y = fmaf(w, f0.y, a.y);
    a.z = fmaf(w, f1.x, a.z); a.w = fmaf(w, f1.y, a.w);
}

__global__ __launch_bounds__(256)
void agg1_csr_kernel() {
    int warp = (blockIdx.x * blockDim.x + threadIdx.x) >> 5;
    int lane = threadIdx.x & 31;
    if (warp >= NNODES) return;
    int e  = g_offs[warp];
    int end = e + g_deg[warp];

    float4 a0 = make_float4(0.f, 0.f, 0.f, 0.f);
    float4 a1 = make_float4(0.f, 0.f, 0.f, 0.f);
    float4 a2 = make_float4(0.f, 0.f, 0.f, 0.f);
    float4 a3 = make_float4(0.f, 0.f, 0.f, 0.f);
    const __half* __restrict__ h = g_h1h;

    for (; e + 3 < end; e += 4) {
        int2 p0 = g_bin[e],     p1 = g_bin[e + 1];
        int2 p2 = g_bin[e + 2], p3 = g_bin[e + 3];
        half4_t v0 = *(const half4_t*)&h[(size_t)p0.x * HDIM + lane * 4];
        half4_t v1 = *(const half4_t*)&h[(size_t)p1.x * HDIM + lane * 4];
        half4_t v2 = *(const half4_t*)&h[(size_t)p2.x * HDIM + lane * 4];
        half4_t v3 = *(const half4_t*)&h[(size_t)p3.x * HDIM + lane * 4];
        acc_h4(a0, __int_as_float(p0.y), v0);
        acc_h4(a1, __int_as_float(p1.y), v1);
        acc_h4(a2, __int_as_float(p2.y), v2);
        acc_h4(a3, __int_as_float(p3.y), v3);
    }
    for (; e < end; e++) {
        int2 p0 = g_bin[e];
        half4_t v0 = *(const half4_t*)&h[(size_t)p0.x * HDIM + lane * 4];
        acc_h4(a0, __int_as_float(p0.y), v0);
    }
    a0.x += a1.x + a2.x + a3.x;
    a0.y += a1.y + a2.y + a3.y;
    a0.z += a1.z + a2.z + a3.z;
    a0.w += a1.w + a2.w + a3.w;
    *(float4*)&g_agg1[(size_t)warp * HDIM + lane * 4] = a0;
}

// ===========================================================================
// GEMM2 via legacy HMMA, 3-split bf16 emu, activation fused in A loader:
//   h2 = act(agg1) @ W2 ; act(v) = relu(v + b1) * (mask >= 0.5 ? 2 : 0)
// CTA: 128(M) x 64(N); 8 warps 4x2; warp tile 32x32; BK=32 double-buffered.
// ===========================================================================
#define G2_BM    128
#define G2_BK    32
#define G2_APL   (G2_BM * G1_LDB * 2)      // 10240 B per A plane
#define G2_BPL   (CDIM * G1_LDB * 2)       // 5120 B per B plane
#define G2_STG   (2 * G2_APL + 2 * G2_BPL) // 30720 B per stage
#define G2_SMEM  (2 * G2_STG)              // 61440 B
#define G2_NCH   (HDIM / G2_BK)            // 4

#define OFF2_AH 0
#define OFF2_AL G2_APL
#define OFF2_BH (2 * G2_APL)
#define OFF2_BL (2 * G2_APL + G2_BPL)

__global__ __launch_bounds__(256)
void gemm2_hmma_kernel(const float* __restrict__ b1, const float* __restrict__ mask,
                       int M) {
    extern __shared__ char smem[];
    const uint32_t sb = smem_u32(smem);
    const int tid  = threadIdx.x;
    const int wid  = tid >> 5;
    const int lane = tid & 31;
    const int wm   = wid >> 1;
    const int wn   = wid & 1;
    const int m0   = blockIdx.x * G2_BM;

    const __nv_bfloat16* __restrict__ bhp = g_w2t_hi;
    const __nv_bfloat16* __restrict__ blp = g_w2t_lo;

    float acc[2][4][4];
    #pragma unroll
    for (int i = 0; i < 2; i++)
        #pragma unroll
        for (int j = 0; j < 4; j++)
            #pragma unroll
            for (int q = 0; q < 4; q++) acc[i][j][q] = 0.f;

    auto ldgA = [&](int k0, float4* ar) {
        #pragma unroll
        for (int p = 0; p < 4; p++) {
            int idx = tid + p * 256;
            int r   = idx >> 3;
            int c4  = idx & 7;
            float4 v = make_float4(0.f, 0.f, 0.f, 0.f);
            if (m0 + r < M) {
                size_t base = (size_t)(m0 + r) * HDIM + k0 + c4 * 4;
                v          = *(const float4*)&g_agg1[base];
                float4 mk  = *(const float4*)&mask[base];
                float4 bb  = *(const float4*)&b1[k0 + c4 * 4];
                v.x = fmaxf(v.x + bb.x, 0.f) * (mk.x >= 0.5f ? 2.f : 0.f);
                v.y = fmaxf(v.y + bb.y, 0.f) * (mk.y >= 0.5f ? 2.f : 0.f);
                v.z = fmaxf(v.z + bb.z, 0.f) * (mk.z >= 0.5f ? 2.f : 0.f);
                v.w = fmaxf(v.w + bb.w, 0.f) * (mk.w >= 0.5f ? 2.f : 0.f);
            }
            ar[p] = v;
        }
    };
    auto stsA = [&](uint32_t stg, const float4* ar) {
        #pragma unroll
        for (int p = 0; p < 4; p++) {
            int idx = tid + p * 256;
            int r   = idx >> 3;
            int c4  = idx & 7;
            uint32_t lo0, lo1;
            uint32_t hi0 = split_pair(ar[p].x, ar[p].y, lo0);
            uint32_t hi1 = split_pair(ar[p].z, ar[p].w, lo1);
            uint32_t off = (uint32_t)(r * (G1_LDB * 2) + c4 * 8);
            *(uint2*)(smem + (stg - sb) + OFF2_AH + off) = make_uint2(hi0, hi1);
            *(uint2*)(smem + (stg - sb) + OFF2_AL + off) = make_uint2(lo0, lo1);
        }
    };
    auto cpB = [&](int k0, uint32_t stg) {
        #pragma unroll
        for (int p = 0; p < 2; p++) {
            int idx = tid + p * 256;
            int pl  = idx >> 8;
            int r   = (idx & 255) >> 2;
            int sg  = idx & 3;
            const __nv_bfloat16* src =
                (pl ? blp : bhp) + (size_t)r * HDIM + k0 + sg * 8;
            uint32_t dst = stg + (pl ? OFF2_BL : OFF2_BH)
                         + (uint32_t)(r * (G1_LDB * 2) + sg * 16);
            CP_ASYNC16(dst, src);
        }
        CP_COMMIT();
    };

    float4 ar[4];
    ldgA(0, ar);
    cpB(0, sb);
    stsA(sb, ar);
    CP_WAIT0();
    __syncthreads();

    const int arow  = (lane & 15);
    const int acol8 = (lane >> 4) * 8;
    const int bg    = lane >> 3;
    const int brow  = ((bg >> 1) * 8) + (lane & 7);
    const int bcol8 = (bg & 1) * 8;

    for (int c = 0; c < G2_NCH; c++) {
        const uint32_t cur = sb + (uint32_t)((c & 1) * G2_STG);
        const uint32_t nxt = sb + (uint32_t)(((c + 1) & 1) * G2_STG);

        if (c + 1 < G2_NCH) {
            ldgA((c + 1) * G2_BK, ar);
            cpB((c + 1) * G2_BK, nxt);
        }

        #pragma unroll
        for (int kk = 0; kk < G2_BK; kk += 16) {
            uint32_t afh[2][4], afl[2][4];
            #pragma unroll
            for (int am = 0; am < 2; am++) {
                uint32_t aoff = (uint32_t)((wm * 32 + am * 16 + arow) * (G1_LDB * 2)
                                           + (kk + acol8) * 2);
                ldsm_x4(afh[am], cur + OFF2_AH + aoff);
                ldsm_x4(afl[am], cur + OFF2_AL + aoff);
            }
            #pragma unroll
            for (int bp = 0; bp < 2; bp++) {
                uint32_t boff = (uint32_t)((wn * 32 + bp * 16 + brow) * (G1_LDB * 2)
                                           + (kk + bcol8) * 2);
                uint32_t bfh[4], bfl[4];
                ldsm_x4(bfh, cur + OFF2_BH + boff);
                ldsm_x4(bfl, cur + OFF2_BL + boff);
                #pragma unroll
                for (int am = 0; am < 2; am++) {
                    #pragma unroll
                    for (int j = 0; j < 2; j++) {
                        float* cc = acc[am][bp * 2 + j];
                        mma_bf16(cc, afh[am], bfh + 2 * j);
                        mma_bf16(cc, afh[am], bfl + 2 * j);
                        mma_bf16(cc, afl[am], bfh + 2 * j);
                    }
                }
            }
        }

        if (c + 1 < G2_NCH) {
            stsA(nxt, ar);
            CP_WAIT0();
        }
        __syncthreads();
    }

    const int erow = lane >> 2;
    const int ecol = (lane & 3) * 2;
    #pragma unroll
    for (int am = 0; am < 2; am++) {
        int r0 = m0 + wm * 32 + am * 16 + erow;
        #pragma unroll
        for (int an = 0; an < 4; an++) {
            int colb = wn * 32 + an * 8 + ecol;
            if (r0 < M)
                *(float2*)&g_h2[(size_t)r0 * CDIM + colb] =
                    make_float2(acc[am][an][0], acc[am][an][1]);
            if (r0 + 8 < M)
                *(float2*)&g_h2[(size_t)(r0 + 8) * CDIM + colb] =
                    make_float2(acc[am][an][2], acc[am][an][3]);
        }
    }
}

// ===========================================================================
// CSR aggregation, layer 2, fused bias + log-softmax, unroll-4 (fp32 h2)
// ===========================================================================
__global__ __launch_bounds__(256)
void agg2_softmax_kernel(const float* __restrict__ b2, float* __restrict__ out) {
    int warp = (blockIdx.x * blockDim.x + threadIdx.x) >> 5;
    int lane = threadIdx.x & 31;
    if (warp >= NNODES) return;
    int e  = g_offs[warp];
    int end = e + g_deg[warp];

    float2 a0 = make_float2(0.f, 0.f), a1 = make_float2(0.f, 0.f);
    float2 a2 = make_float2(0.f, 0.f), a3 = make_float2(0.f, 0.f);
    const float* __restrict__ h = g_h2;

    for (; e + 3 < end; e += 4) {
        int2 p0 = g_bin[e],     p1 = g_bin[e + 1];
        int2 p2 = g_bin[e + 2], p3 = g_bin[e + 3];
        float w0 = __int_as_float(p0.y), w1 = __int_as_float(p1.y);
        float w2 = __int_as_float(p2.y), w3 = __int_as_float(p3.y);
        float2 v0 = *(const float2*)&h[(size_t)p0.x * CDIM + lane * 2];
        float2 v1 = *(const float2*)&h[(size_t)p1.x * CDIM + lane * 2];
        float2 v2 = *(const float2*)&h[(size_t)p2.x * CDIM + lane * 2];
        float2 v3 = *(const float2*)&h[(size_t)p3.x * CDIM + lane * 2];
        a0.x = fmaf(w0, v0.x, a0.x); a0.y = fmaf(w0, v0.y, a0.y);
        a1.x = fmaf(w1, v1.x, a1.x); a1.y = fmaf(w1, v1.y, a1.y);
        a2.x = fmaf(w2, v2.x, a2.x); a2.y = fmaf(w2, v2.y, a2.y);
        a3.x = fmaf(w3, v3.x, a3.x); a3.y = fmaf(w3, v3.y, a3.y);
    }
    for (; e < end; e++) {
        int2 p0 = g_bin[e];
        float w0 = __int_as_float(p0.y);
        float2 v0 = *(const float2*)&h[(size_t)p0.x * CDIM + lane * 2];
        a0.x = fmaf(w0, v0.x, a0.x); a0.y = fmaf(w0, v0.y, a0.y);
    }
    float2 bb = *(const float2*)&b2[lane * 2];
    float vx = a0.x + a1.x + a2.x + a3.x + bb.x;
    float vy = a0.y + a1.y + a2.y + a3.y + bb.y;

    float m = fmaxf(vx, vy);
    #pragma unroll
    for (int o = 16; o > 0; o >>= 1) m = fmaxf(m, __shfl_xor_sync(0xFFFFFFFFu, m, o));
    float s = expf(vx - m) + expf(vy - m);
    #pragma unroll
    for (int o = 16; o > 0; o >>= 1) s += __shfl_xor_sync(0xFFFFFFFFu, s, o);
    float lse = m + logf(s);
    *(float2*)&out[(size_t)warp * CDIM + lane * 2] = make_float2(vx - lse, vy - lse);
}

// ===========================================================================
// Launch — CSR build + w2prep forked onto a second stream, under GEMM1.
// ===========================================================================
extern "C" void kernel_launch(void* const* d_in, const int* in_sizes, int n_in,
                              void* d_out, int out_size) {
    const float* x    = (const float*)d_in[0];   // [N, 512]
    const float* ew   = (const float*)d_in[1];   // [E]
    const float* W1   = (const float*)d_in[2];   // [512, 128]
    const float* b1   = (const float*)d_in[3];   // [128]
    const float* W2   = (const float*)d_in[4];   // [128, 64]
    const float* b2   = (const float*)d_in[5];   // [64]
    const float* mask = (const float*)d_in[6];   // [N, 128]
    const int*   ei   = (const int*)d_in[7];     // [2, E]
    float* out = (float*)d_out;

    const int N = NNODES, E = NEDGES;
    const int* src = ei;
    const int* dst = ei + E;

    static cudaStream_t s2 = nullptr;
    static cudaEvent_t  evFork = nullptr, evJoin = nullptr;
    if (!s2) {
        cudaStreamCreateWithFlags(&s2, cudaStreamNonBlocking);
        cudaEventCreateWithFlags(&evFork, cudaEventDisableTiming);
        cudaEventCreateWithFlags(&evJoin, cudaEventDisableTiming);
        cudaFuncSetAttribute(gemm1_hmma_kernel,
                             cudaFuncAttributeMaxDynamicSharedMemorySize, G1_SMEM);
        cudaFuncSetAttribute(gemm2_hmma_kernel,
                             cudaFuncAttributeMaxDynamicSharedMemorySize, G2_SMEM);
    }

    // --- fork: CSR build + W2 prep on s2 (all hidden under gemm1) ---
    cudaEventRecord(evFork, 0);
    cudaStreamWaitEvent(s2, evFork, 0);

    w2prep_kernel<<<(CDIM * HDIM + 255) / 256, 256, 0, s2>>>(W2);
    zero_deg_kernel<<<(N + 255) / 256, 256, 0, s2>>>();
    hist_kernel<<<(E + 255) / 256, 256, 0, s2>>>(dst);
    scan1_kernel<<<NB_SCAN, SCAN_BLK, 0, s2>>>();
    scan2_kernel<<<1, SCAN_BLK, 0, s2>>>();
    scan3_kernel<<<NB_SCAN, SCAN_BLK, 0, s2>>>();
    bin_kernel<<<(E + 255) / 256, 256, 0, s2>>>(src, dst, ew);
    cudaEventRecord(evJoin, s2);

    // --- main stream: W1 fp16 prep, then single-MMA fp16 GEMM1 ---
    w1prep_kernel<<<(HDIM * FIN + 255) / 256, 256>>>(W1);
    gemm1_hmma_kernel<<<(N + G1_BM - 1) / G1_BM, 256, G1_SMEM>>>(x, N);

    // --- join: aggregation needs both h1 and the CSR bins ---
    cudaStreamWaitEvent(0, evJoin, 0);
    agg1_csr_kernel<<<(N * 32 + 255) / 256, 256>>>();

    // --- layer 2 (HMMA bf16 3-split, activation fused in loader) ---
    gemm2_hmma_kernel<<<(N + G2_BM - 1) / G2_BM, 256, G2_SMEM>>>(b1, mask, N);
    agg2_softmax_kernel<<<(N * 32 + 255) / 256, 256>>>(b2, out);
}